// round 11
// baseline (speedup 1.0000x reference)
#include <cuda_runtime.h>
#include <cuda_bf16.h>
#include <math.h>
#include <stdint.h>

#define HU       250
#define KPAD     256
#define SPB      16          // samples per block -> M = 128 rows
#define NTHREADS 1024        // 32 warps: warp = (stripe 0..7, n-quarter 0..3)
#define NHID     6
#define NCHUNK   8           // k chunks of 32 per layer
#define TOTCH    (NHID*NCHUNK)

// ---- smem layout (relative to 1024-aligned base) ----
#define A0_OFF   0            // A hi: 128 rows x 512B (256 bf16, XOR-swizzled)
#define A1_OFF   65536        // A lo
#define B_OFF    131072       // 3 stages x 32KB (hi 16KB + lo 16KB each)
#define CTRL_OFF 229376       // full[3] @ +0,8,16 ; cnt[3] @ +32
#define ZSH_OFF  (B_OFF)      // reuse B stage 0 after mainloop
#define SMEM_BYTES (CTRL_OFF + 64 + 1024)

// pre-split weight images: [layer][chunk][term][n=256][k=32 swizzled] (hi+lo contiguous)
__device__ __nv_bfloat16 g_B[NHID][NCHUNK][2][256][32];

// ---------------- helpers ----------------
__device__ __forceinline__ void mbar_init(uint32_t m, uint32_t cnt) {
    asm volatile("mbarrier.init.shared.b64 [%0], %1;" :: "r"(m), "r"(cnt) : "memory");
}
__device__ __forceinline__ void mbar_expect(uint32_t m, uint32_t bytes) {
    asm volatile("mbarrier.arrive.expect_tx.shared.b64 _, [%0], %1;" :: "r"(m), "r"(bytes) : "memory");
}
__device__ __forceinline__ void mbar_wait(uint32_t m, uint32_t ph) {
    asm volatile(
        "{\n\t.reg .pred P1;\n\t"
        "WAIT_LOOP_%=:\n\t"
        "mbarrier.try_wait.parity.acquire.cta.shared::cta.b64 P1, [%0], %1, 0x989680;\n\t"
        "@P1 bra.uni WAIT_DONE_%=;\n\t"
        "bra.uni WAIT_LOOP_%=;\n\t"
        "WAIT_DONE_%=:\n\t}"
        :: "r"(m), "r"(ph) : "memory");
}
__device__ __forceinline__ void bulk_g2s(uint32_t dst, const void* src, uint32_t bytes, uint32_t mbar) {
    asm volatile("cp.async.bulk.shared::cluster.global.mbarrier::complete_tx::bytes [%0], [%1], %2, [%3];"
                 :: "r"(dst), "l"(src), "r"(bytes), "r"(mbar) : "memory");
}
__device__ __forceinline__ void bar_stripe(int id) {
    asm volatile("bar.sync %0, 128;" :: "r"(id) : "memory");
}
__device__ __forceinline__ void ldmx4(uint32_t& r0, uint32_t& r1, uint32_t& r2, uint32_t& r3, uint32_t addr) {
    asm volatile("ldmatrix.sync.aligned.m8n8.x4.shared.b16 {%0,%1,%2,%3}, [%4];"
                 : "=r"(r0), "=r"(r1), "=r"(r2), "=r"(r3) : "r"(addr));
}
__device__ __forceinline__ void mma_bf16(float* d, uint32_t a0, uint32_t a1, uint32_t a2, uint32_t a3,
                                         uint32_t b0, uint32_t b1) {
    asm volatile("mma.sync.aligned.m16n8k16.row.col.f32.bf16.bf16.f32 "
                 "{%0,%1,%2,%3}, {%4,%5,%6,%7}, {%8,%9}, {%0,%1,%2,%3};"
                 : "+f"(d[0]), "+f"(d[1]), "+f"(d[2]), "+f"(d[3])
                 : "r"(a0), "r"(a1), "r"(a2), "r"(a3), "r"(b0), "r"(b1));
}
__device__ __forceinline__ uint32_t pack_bf16x2(float lo, float hi) {
    __nv_bfloat16 a = __float2bfloat16(lo);
    __nv_bfloat16 b = __float2bfloat16(hi);
    return ((uint32_t)*(unsigned short*)&b << 16) | (uint32_t)*(unsigned short*)&a;
}
// h given precomputed f = tanh(c*(z_val+bias))
__device__ __forceinline__ float elemh2(int ch, float c, float z, float f, float zx, float zy) {
    float dd = c * (1.0f - f * f);
    float m2 = -2.0f * c * f;
    float t2 = (ch == 4) ? zx * zx : (ch == 5) ? zy * zy : (ch == 6) ? zy * zx : 0.0f;
    float h  = fmaf(m2 * dd, t2, dd * z);
    if (ch == 0) h = f;
    if (ch == 7) h = 0.0f;
    return h;
}

// ---------------- prep: split + transpose + swizzle W_h ----------------
__global__ void prep_kernel(const float* __restrict__ W_h) {
    int idx = blockIdx.x * blockDim.x + threadIdx.x;
    if (idx >= NHID * NCHUNK * 256 * 32) return;
    int kk = idx & 31;
    int n  = (idx >> 5) & 255;
    int kc = (idx >> 13) & 7;
    int l  = idx >> 16;
    int kg = kc * 32 + kk;
    float w = (n < HU && kg < HU) ? W_h[(l * HU + kg) * HU + n] : 0.0f;
    __nv_bfloat16 hi = __float2bfloat16(w);
    __nv_bfloat16 lo = __float2bfloat16(w - __bfloat162float(hi));
    int u  = kk >> 3;
    int up = u ^ ((n >> 1) & 3);
    int off = up * 8 + (kk & 7);
    g_B[l][kc][0][n][off] = hi;
    g_B[l][kc][1][n][off] = lo;
}

// ---------------- main kernel ----------------
__global__ __launch_bounds__(NTHREADS, 1)
void pinn_mma_kernel(const float* __restrict__ x,
                     const float* __restrict__ y,
                     const float* __restrict__ t,
                     const float* __restrict__ W_in,
                     const float* __restrict__ b_in,
                     const float* __restrict__ b_h,
                     const float* __restrict__ W_out,
                     const float* __restrict__ b_out,
                     const float* __restrict__ act,
                     float* __restrict__ out,
                     int N)
{
    extern __shared__ char smraw[];
    char* sm = (char*)(((uintptr_t)smraw + 1023) & ~(uintptr_t)1023);
    uint32_t smb;
    asm("{ .reg .u64 tmp; cvta.to.shared.u64 tmp, %1; cvt.u32.u64 %0, tmp; }"
        : "=r"(smb) : "l"(sm));

    const int tid = threadIdx.x;
    const int wid = tid >> 5;          // 0..31
    const int lid = tid & 31;
    const int sw  = wid >> 2;          // stripe 0..7
    const int nq  = wid & 3;           // n-quarter 0..3
    const int n0g = blockIdx.x * SPB;
    int* cnt_sm = (int*)(sm + CTRL_OFF + 32);

    // init barriers + issue prologue TMA immediately (overlaps input phase)
    if (tid == 0) {
        #pragma unroll
        for (int s = 0; s < 3; ++s) {
            mbar_init(smb + CTRL_OFF + s * 8, 1);   // full
            cnt_sm[s] = 0;
        }
        #pragma unroll
        for (int s = 0; s < 3; ++s) {
            uint32_t dst = smb + B_OFF + s * 32768;
            mbar_expect(smb + CTRL_OFF + s * 8, 32768);
            bulk_g2s(dst, &g_B[0][s][0][0][0], 32768, smb + CTRL_OFF + s * 8);
        }
    }

    // -------- input layer: fill A0/A1 (bf16 split, swizzled) --------
    {
        const float c0 = 10.0f * __ldg(&act[0]);
        for (int idx = tid; idx < SPB * KPAD; idx += NTHREADS) {
            int s = idx >> 8, n = idx & 255;
            float hv[8] = {0.f, 0.f, 0.f, 0.f, 0.f, 0.f, 0.f, 0.f};
            if (n < HU) {
                int gn = n0g + s;
                float px = 0.f, py = 0.f, pt = 0.f;
                if (gn < N) { px = x[gn]; py = y[gn]; pt = t[gn]; }
                float w0 = __ldg(&W_in[n]);
                float w1 = __ldg(&W_in[HU + n]);
                float w2 = __ldg(&W_in[2 * HU + n]);
                float bj = __ldg(&b_in[n]);
                float z = px * w0 + py * w1 + pt * w2 + bj;
                float f = tanhf(c0 * z);
                float d = c0 * (1.0f - f * f);
                float fx = d * w0, fy = d * w1;
                float m2 = -2.0f * c0 * f;
                hv[0] = f;  hv[1] = fx; hv[2] = fy; hv[3] = d * w2;
                hv[4] = m2 * fx * w0; hv[5] = m2 * fy * w1; hv[6] = m2 * fy * w0;
            }
            #pragma unroll
            for (int c = 0; c < 8; ++c) {
                int row = 8 * s + c;
                uint32_t addr = (uint32_t)(row * 512 + (((n >> 3) ^ (row & 7)) << 4) + (n & 7) * 2);
                float v = hv[c];
                __nv_bfloat16 hi = __float2bfloat16(v);
                *(__nv_bfloat16*)(sm + A0_OFF + addr) = hi;
                *(__nv_bfloat16*)(sm + A1_OFF + addr) = __float2bfloat16(v - __bfloat162float(hi));
            }
        }
    }
    __syncthreads();

    // lane-constant address pieces
    const int arow = 16 * sw + ((lid >> 3) & 1) * 8 + (lid & 7);
    const int bln  = ((lid >> 3) & 1) * 8 + (lid & 7);
    const int khalf = (lid >> 4);
    const int l7    = lid & 7;
    const uint32_t bswz = (uint32_t)((bln >> 1) & 3);
    const uint32_t abase = smb + A0_OFF + (uint32_t)(arow * 512);
    const uint32_t bbase_n = (uint32_t)((nq * 64 + bln) * 64);
    const int wks = wid & 1;            // warp-specific ks order
    const int wj2 = (wid >> 1) & 3;     // warp-specific j2 rotation

    #pragma unroll 1
    for (int l = 0; l < NHID; ++l) {
        float d[8][4];
        #pragma unroll
        for (int j = 0; j < 8; ++j) {
            d[j][0] = 0.f; d[j][1] = 0.f; d[j][2] = 0.f; d[j][3] = 0.f;
        }

        #pragma unroll 1
        for (int c = 0; c < NCHUNK; ++c) {
            const int ci = l * NCHUNK + c;
            const int v  = ci / 3;
            const int st = ci - v * 3;
            mbar_wait(smb + CTRL_OFF + st * 8, (uint32_t)(v & 1));

            const uint32_t Bst = smb + B_OFF + st * 32768;
            #pragma unroll
            for (int ksx = 0; ksx < 2; ++ksx) {
                const int ks = ksx ^ wks;
                int aku = c * 4 + ks * 2 + khalf;
                uint32_t aaddr = abase + (uint32_t)((aku ^ l7) << 4);
                uint32_t a0, a1, a2, a3, e0, e1, e2, e3;
                ldmx4(a0, a1, a2, a3, aaddr);
                ldmx4(e0, e1, e2, e3, aaddr + (A1_OFF - A0_OFF));

                uint32_t u = (uint32_t)(ks * 2 + khalf);
                uint32_t blane = Bst + bbase_n + ((u ^ bswz) << 4);
                #pragma unroll
                for (int jx = 0; jx < 4; ++jx) {
                    const int j2 = (jx + wj2) & 3;   // warp-rotated start, zero extra regs
                    uint32_t b0, b1, b2, b3;
                    ldmx4(b0, b1, b2, b3, blane + (uint32_t)(j2 * 1024));
                    mma_bf16(d[2 * j2],     a0, a1, a2, a3, b0, b2);
                    mma_bf16(d[2 * j2 + 1], a0, a1, a2, a3, b1, b3);
                    mma_bf16(d[2 * j2],     e0, e1, e2, e3, b0, b2);   // A1*B0
                    mma_bf16(d[2 * j2 + 1], e0, e1, e2, e3, b1, b3);
                    uint32_t c0, c1, c2, c3;
                    ldmx4(c0, c1, c2, c3, blane + 16384u + (uint32_t)(j2 * 1024));
                    mma_bf16(d[2 * j2],     a0, a1, a2, a3, c0, c2);   // A0*B1
                    mma_bf16(d[2 * j2 + 1], a0, a1, a2, a3, c1, c3);
                }
            }
            // last-arriver issues the refill for chunk ci+3 into this stage
            if (lid == 0) {
                int old = atomicAdd(&cnt_sm[st], 1);
                if (old == 31) {
                    cnt_sm[st] = 0;
                    int cr = ci + 3;
                    if (cr < TOTCH) {
                        int l2 = cr >> 3, c2 = cr & 7;
                        uint32_t dst = smb + B_OFF + st * 32768;
                        mbar_expect(smb + CTRL_OFF + st * 8, 32768);
                        bulk_g2s(dst, &g_B[l2][c2][0][0][0], 32768, smb + CTRL_OFF + st * 8);
                    }
                }
            }
        }

        // -------- epilogue --------
        if (l == NHID - 1) __syncthreads();
        else               bar_stripe(1 + sw);

        const float cl = 10.0f * __ldg(&act[l + 1]);
        const int ch   = lid >> 2;
        const int lq   = lid & 3;
        const int srcv = lq, srcx = 4 | lq, srcy = 8 | lq;
        const int rA = 16 * sw + ch, rB = 16 * sw + 8 + ch;
        const int sA = 2 * sw, sB = 2 * sw + 1;
        float* hsb = (float*)sm;

        #pragma unroll
        for (int j = 0; j < 8; ++j) {
            int n0 = nq * 64 + 8 * j + 2 * lq;
            float bv0 = 0.f, bv1 = 0.f;
            if (n0 < HU) {
                float2 bb = *(const float2*)&b_h[l * HU + n0];
                bv0 = bb.x; bv1 = bb.y;
            }

            float zv0 = __shfl_sync(0xffffffffu, d[j][0], srcv);
            float zv1 = __shfl_sync(0xffffffffu, d[j][1], srcv);
            float wv0 = __shfl_sync(0xffffffffu, d[j][2], srcv);
            float wv1 = __shfl_sync(0xffffffffu, d[j][3], srcv);

            // one tanh per lane, deduped across the 8 channel-lanes of this quad
            int e = ch & 3;
            float arg = (e == 0) ? (zv0 + bv0) : (e == 1) ? (zv1 + bv1)
                      : (e == 2) ? (wv0 + bv0) : (wv1 + bv1);
            float tres = tanhf(cl * arg);
            float fA0 = __shfl_sync(0xffffffffu, tres, lq);
            float fA1 = __shfl_sync(0xffffffffu, tres, 4  | lq);
            float fB0 = __shfl_sync(0xffffffffu, tres, 8  | lq);
            float fB1 = __shfl_sync(0xffffffffu, tres, 12 | lq);

            float zx0 = __shfl_sync(0xffffffffu, d[j][0], srcx);
            float zx1 = __shfl_sync(0xffffffffu, d[j][1], srcx);
            float zy0 = __shfl_sync(0xffffffffu, d[j][0], srcy);
            float zy1 = __shfl_sync(0xffffffffu, d[j][1], srcy);
            float hA0 = elemh2(ch, cl, d[j][0], fA0, zx0, zy0);
            float hA1 = elemh2(ch, cl, d[j][1], fA1, zx1, zy1);

            float wx0 = __shfl_sync(0xffffffffu, d[j][2], srcx);
            float wx1 = __shfl_sync(0xffffffffu, d[j][3], srcx);
            float wy0 = __shfl_sync(0xffffffffu, d[j][2], srcy);
            float wy1 = __shfl_sync(0xffffffffu, d[j][3], srcy);
            float hB0 = elemh2(ch, cl, d[j][2], fB0, wx0, wy0);
            float hB1 = elemh2(ch, cl, d[j][3], fB1, wx1, wy1);

            if (n0 >= HU)     { hA0 = 0.f; hB0 = 0.f; }
            if (n0 + 1 >= HU) { hA1 = 0.f; hB1 = 0.f; }

            int unit = nq * 8 + j;
            if (l < NHID - 1) {
                uint32_t offA = (uint32_t)(rA * 512 + ((unit ^ (rA & 7)) << 4) + (n0 & 7) * 2);
                uint32_t offB = (uint32_t)(rB * 512 + ((unit ^ (rB & 7)) << 4) + (n0 & 7) * 2);
                float lA0 = hA0 - __bfloat162float(__float2bfloat16(hA0));
                float lA1 = hA1 - __bfloat162float(__float2bfloat16(hA1));
                float lB0 = hB0 - __bfloat162float(__float2bfloat16(hB0));
                float lB1 = hB1 - __bfloat162float(__float2bfloat16(hB1));
                *(uint32_t*)(sm + A0_OFF + offA) = pack_bf16x2(hA0, hA1);
                *(uint32_t*)(sm + A1_OFF + offA) = pack_bf16x2(lA0, lA1);
                *(uint32_t*)(sm + A0_OFF + offB) = pack_bf16x2(hB0, hB1);
                *(uint32_t*)(sm + A1_OFF + offB) = pack_bf16x2(lB0, lB1);
            } else {
                if (n0 < HU) {
                    hsb[(sA * 256 + n0) * 8 + ch] = hA0;
                    hsb[(sB * 256 + n0) * 8 + ch] = hB0;
                }
                if (n0 + 1 < HU) {
                    hsb[(sA * 256 + n0 + 1) * 8 + ch] = hA1;
                    hsb[(sB * 256 + n0 + 1) * 8 + ch] = hB1;
                }
            }
        }
        if (l < NHID - 1) bar_stripe(1 + sw);
    }
    __syncthreads();   // hsb complete

    // -------- output layer: 16 samples x 4 outs x 7 channels --------
    {
        float* hsb = (float*)sm;
        float* zsh = (float*)(sm + ZSH_OFF);
        for (int idx = tid; idx < SPB * 28; idx += NTHREADS) {
            int s = idx / 28, k2 = idx % 28, o = k2 / 7, c = k2 % 7;
            float acc = (c == 0) ? __ldg(&b_out[o]) : 0.f;
            for (int n = 0; n < HU; ++n)
                acc += hsb[(s * 256 + n) * 8 + c] * __ldg(&W_out[n * 4 + o]);
            zsh[(s * 4 + o) * 8 + c] = acc;
        }
    }
    __syncthreads();

    // -------- residual assembly --------
    if (tid < SPB) {
        int s = tid, n = n0g + s;
        if (n < N) {
            float* zsh = (float*)(sm + ZSH_OFF);
            #define Z(o, c) zsh[((s * 4) + (o)) * 8 + (c)]
            float u = Z(0,0), ux = Z(0,1), uy = Z(0,2), ut = Z(0,3), uxx = Z(0,4), uyy = Z(0,5);
            float v = Z(1,0), vx = Z(1,1), vy = Z(1,2), vt = Z(1,3), vxx = Z(1,4), vyy = Z(1,5);
            float pe  = expf(Z(2,0));
            float p_x = pe * Z(2,1);
            float p_y = pe * Z(2,2);
            float z3  = Z(3,0);
            float aa  = 1.0f / (1.0f + expf(-z3));
            float da  = aa * (1.0f - aa);
            float zax = Z(3,1), zay = Z(3,2), zat = Z(3,3);
            float ax = da * zax, ay = da * zay, at2 = da * zat;
            float om = da * (1.0f - 2.0f * aa);
            float axx = om * zax * zax + da * Z(3,4);
            float ayy = om * zay * zay + da * Z(3,5);
            float axy = om * zax * zay + da * Z(3,6);
            #undef Z
            const float MU1 = 1.0f, MU2 = 10.0f;
            const float RHO1 = 100.0f, RHO2 = 1000.0f, RHO_REF = 1000.0f;
            const float ONE_WE = 24.5f / 500.0f;
            const float ONE_FR = 0.49f;
            const float RE_DEN = 500.0f;
            const float EPSC = 2.2204460492503131e-16f;

            float mu  = MU2 + (MU1 - MU2) * aa;
            float mux = (MU1 - MU2) * ax;
            float muy = (MU1 - MU2) * ay;
            float rho = RHO2 + (RHO1 - RHO2) * aa;
            float g   = sqrtf(ax * ax + ay * ay + EPSC);
            float g3  = g * g * g;
            float curv = -((axx + ayy) / g -
                           (ax * ax * axx + ay * ay * ayy + 2.0f * ax * ay * axy) / g3);
            float oRe  = mu  / RE_DEN;
            float oRex = mux / RE_DEN;
            float oRey = muy / RE_DEN;
            float rr   = rho / RHO_REF;

            float PDE_m = ux + vy;
            float PDE_a = at2 + u * ax + v * ay;
            float PDE_u = (ut + u * ux + v * uy) * rr + p_x - ONE_WE * curv * ax
                        - oRe * (uxx + uyy) - 2.0f * oRex * ux - oRey * (uy + vx);
            float PDE_v = (vt + u * vx + v * vy) * rr + p_y - ONE_WE * curv * ay
                        - oRe * (vxx + vyy) - rr * ONE_FR - 2.0f * oRey * vy - oRex * (uy + vx);

            out[0 * N + n] = PDE_m;
            out[1 * N + n] = PDE_u;
            out[2 * N + n] = PDE_v;
            out[3 * N + n] = PDE_a;
        }
    }
    __syncthreads();
    if (tid == 0) {
        #pragma unroll
        for (int s = 0; s < 3; ++s)
            asm volatile("mbarrier.inval.shared.b64 [%0];" :: "r"(smb + CTRL_OFF + s * 8) : "memory");
    }
}

extern "C" void kernel_launch(void* const* d_in, const int* in_sizes, int n_in,
                              void* d_out, int out_size)
{
    const float* x     = (const float*)d_in[0];
    const float* y     = (const float*)d_in[1];
    const float* t     = (const float*)d_in[2];
    const float* W_in  = (const float*)d_in[3];
    const float* b_in  = (const float*)d_in[4];
    const float* W_h   = (const float*)d_in[5];
    const float* b_h   = (const float*)d_in[6];
    const float* W_out = (const float*)d_in[7];
    const float* b_out = (const float*)d_in[8];
    const float* act   = (const float*)d_in[9];
    float* out = (float*)d_out;
    int N = in_sizes[0];

    cudaFuncSetAttribute(pinn_mma_kernel,
                         cudaFuncAttributeMaxDynamicSharedMemorySize, SMEM_BYTES);

    prep_kernel<<<(NHID * NCHUNK * 256 * 32 + 255) / 256, 256>>>(W_h);

    int blocks = (N + SPB - 1) / SPB;
    pinn_mma_kernel<<<blocks, NTHREADS, SMEM_BYTES>>>(
        x, y, t, W_in, b_in, b_h, W_out, b_out, act, out, N);
}

// round 13
// speedup vs baseline: 2.2637x; 2.2637x over previous
#include <cuda_runtime.h>
#include <cuda_bf16.h>
#include <math.h>
#include <stdint.h>

#define HU       250
#define KPAD     256
#define SPB      16          // samples per block -> M = 128 rows
#define NTHREADS 1024        // 32 warps: warp = (stripe 0..7, n-quarter 0..3)
#define NHID     6
#define NCHUNK   8           // k chunks of 32 per layer
#define TOTCH    (NHID*NCHUNK)

// ---- smem layout (relative to 1024-aligned base) ----
#define A0_OFF   0            // A hi: 128 rows x 512B (256 bf16, XOR-swizzled)
#define A1_OFF   65536        // A lo
#define B_OFF    131072       // 3 stages x 32KB (hi 16KB + lo 16KB each)
#define CTRL_OFF 229376       // full[3] @ +0,8,16 ; cnt[3] @ +32
#define ZSH_OFF  (B_OFF)      // reuse B stage 0 after mainloop
#define SMEM_BYTES (CTRL_OFF + 64 + 1024)

// pre-split weight images: [layer][chunk][term][n=256][k=32 swizzled] (hi+lo contiguous)
__device__ __nv_bfloat16 g_B[NHID][NCHUNK][2][256][32];

// ---------------- helpers ----------------
__device__ __forceinline__ void mbar_init(uint32_t m, uint32_t cnt) {
    asm volatile("mbarrier.init.shared.b64 [%0], %1;" :: "r"(m), "r"(cnt) : "memory");
}
__device__ __forceinline__ void mbar_expect(uint32_t m, uint32_t bytes) {
    asm volatile("mbarrier.arrive.expect_tx.shared.b64 _, [%0], %1;" :: "r"(m), "r"(bytes) : "memory");
}
__device__ __forceinline__ void mbar_wait(uint32_t m, uint32_t ph) {
    asm volatile(
        "{\n\t.reg .pred P1;\n\t"
        "WAIT_LOOP_%=:\n\t"
        "mbarrier.try_wait.parity.acquire.cta.shared::cta.b64 P1, [%0], %1, 0x989680;\n\t"
        "@P1 bra.uni WAIT_DONE_%=;\n\t"
        "bra.uni WAIT_LOOP_%=;\n\t"
        "WAIT_DONE_%=:\n\t}"
        :: "r"(m), "r"(ph) : "memory");
}
__device__ __forceinline__ void bulk_g2s(uint32_t dst, const void* src, uint32_t bytes, uint32_t mbar) {
    asm volatile("cp.async.bulk.shared::cluster.global.mbarrier::complete_tx::bytes [%0], [%1], %2, [%3];"
                 :: "r"(dst), "l"(src), "r"(bytes), "r"(mbar) : "memory");
}
__device__ __forceinline__ void bar_stripe(int id) {
    asm volatile("bar.sync %0, 128;" :: "r"(id) : "memory");   // 4 warps per stripe = 128 threads
}
__device__ __forceinline__ void ldmx4(uint32_t& r0, uint32_t& r1, uint32_t& r2, uint32_t& r3, uint32_t addr) {
    asm volatile("ldmatrix.sync.aligned.m8n8.x4.shared.b16 {%0,%1,%2,%3}, [%4];"
                 : "=r"(r0), "=r"(r1), "=r"(r2), "=r"(r3) : "r"(addr));
}
__device__ __forceinline__ void mma_bf16(float* d, uint32_t a0, uint32_t a1, uint32_t a2, uint32_t a3,
                                         uint32_t b0, uint32_t b1) {
    asm volatile("mma.sync.aligned.m16n8k16.row.col.f32.bf16.bf16.f32 "
                 "{%0,%1,%2,%3}, {%4,%5,%6,%7}, {%8,%9}, {%0,%1,%2,%3};"
                 : "+f"(d[0]), "+f"(d[1]), "+f"(d[2]), "+f"(d[3])
                 : "r"(a0), "r"(a1), "r"(a2), "r"(a3), "r"(b0), "r"(b1));
}
__device__ __forceinline__ uint32_t pack_bf16x2(float lo, float hi) {
    __nv_bfloat16 a = __float2bfloat16(lo);
    __nv_bfloat16 b = __float2bfloat16(hi);
    return ((uint32_t)*(unsigned short*)&b << 16) | (uint32_t)*(unsigned short*)&a;
}
// h given precomputed f = tanh(c*(z_val+bias))
__device__ __forceinline__ float elemh2(int ch, float c, float z, float f, float zx, float zy) {
    float dd = c * (1.0f - f * f);
    float m2 = -2.0f * c * f;
    float t2 = (ch == 4) ? zx * zx : (ch == 5) ? zy * zy : (ch == 6) ? zy * zx : 0.0f;
    float h  = fmaf(m2 * dd, t2, dd * z);
    if (ch == 0) h = f;
    if (ch == 7) h = 0.0f;
    return h;
}

// ---------------- prep: split + transpose + swizzle W_h ----------------
__global__ void prep_kernel(const float* __restrict__ W_h) {
    int idx = blockIdx.x * blockDim.x + threadIdx.x;
    if (idx >= NHID * NCHUNK * 256 * 32) return;
    int kk = idx & 31;
    int n  = (idx >> 5) & 255;
    int kc = (idx >> 13) & 7;
    int l  = idx >> 16;
    int kg = kc * 32 + kk;
    float w = (n < HU && kg < HU) ? W_h[(l * HU + kg) * HU + n] : 0.0f;
    __nv_bfloat16 hi = __float2bfloat16(w);
    __nv_bfloat16 lo = __float2bfloat16(w - __bfloat162float(hi));
    int u  = kk >> 3;
    int up = u ^ ((n >> 1) & 3);
    int off = up * 8 + (kk & 7);
    g_B[l][kc][0][n][off] = hi;
    g_B[l][kc][1][n][off] = lo;
}

// ---------------- main kernel ----------------
__global__ __launch_bounds__(NTHREADS, 1)
void pinn_mma_kernel(const float* __restrict__ x,
                     const float* __restrict__ y,
                     const float* __restrict__ t,
                     const float* __restrict__ W_in,
                     const float* __restrict__ b_in,
                     const float* __restrict__ b_h,
                     const float* __restrict__ W_out,
                     const float* __restrict__ b_out,
                     const float* __restrict__ act,
                     float* __restrict__ out,
                     int N)
{
    extern __shared__ char smraw[];
    char* sm = (char*)(((uintptr_t)smraw + 1023) & ~(uintptr_t)1023);
    uint32_t smb;
    asm("{ .reg .u64 tmp; cvta.to.shared.u64 tmp, %1; cvt.u32.u64 %0, tmp; }"
        : "=r"(smb) : "l"(sm));

    const int tid = threadIdx.x;
    const int wid = tid >> 5;          // 0..31
    const int lid = tid & 31;
    const int sw  = wid >> 2;          // stripe 0..7
    const int nq  = wid & 3;           // n-quarter 0..3
    const int n0g = blockIdx.x * SPB;
    int* cnt_sm = (int*)(sm + CTRL_OFF + 32);

    // init barriers + issue prologue TMA immediately (overlaps input phase)
    if (tid == 0) {
        #pragma unroll
        for (int s = 0; s < 3; ++s) {
            mbar_init(smb + CTRL_OFF + s * 8, 1);   // full
            cnt_sm[s] = 0;
        }
        #pragma unroll
        for (int s = 0; s < 3; ++s) {
            uint32_t dst = smb + B_OFF + s * 32768;
            mbar_expect(smb + CTRL_OFF + s * 8, 32768);
            bulk_g2s(dst, &g_B[0][s][0][0][0], 32768, smb + CTRL_OFF + s * 8);
        }
    }

    // -------- input layer: fill A0/A1 (bf16 split, swizzled) --------
    {
        const float c0 = 10.0f * __ldg(&act[0]);
        for (int idx = tid; idx < SPB * KPAD; idx += NTHREADS) {
            int s = idx >> 8, n = idx & 255;
            float hv[8] = {0.f, 0.f, 0.f, 0.f, 0.f, 0.f, 0.f, 0.f};
            if (n < HU) {
                int gn = n0g + s;
                float px = 0.f, py = 0.f, pt = 0.f;
                if (gn < N) { px = x[gn]; py = y[gn]; pt = t[gn]; }
                float w0 = __ldg(&W_in[n]);
                float w1 = __ldg(&W_in[HU + n]);
                float w2 = __ldg(&W_in[2 * HU + n]);
                float bj = __ldg(&b_in[n]);
                float z = px * w0 + py * w1 + pt * w2 + bj;
                float f = tanhf(c0 * z);
                float d = c0 * (1.0f - f * f);
                float fx = d * w0, fy = d * w1;
                float m2 = -2.0f * c0 * f;
                hv[0] = f;  hv[1] = fx; hv[2] = fy; hv[3] = d * w2;
                hv[4] = m2 * fx * w0; hv[5] = m2 * fy * w1; hv[6] = m2 * fy * w0;
            }
            #pragma unroll
            for (int c = 0; c < 8; ++c) {
                int row = 8 * s + c;
                uint32_t addr = (uint32_t)(row * 512 + (((n >> 3) ^ (row & 7)) << 4) + (n & 7) * 2);
                float v = hv[c];
                __nv_bfloat16 hi = __float2bfloat16(v);
                *(__nv_bfloat16*)(sm + A0_OFF + addr) = hi;
                *(__nv_bfloat16*)(sm + A1_OFF + addr) = __float2bfloat16(v - __bfloat162float(hi));
            }
        }
    }
    __syncthreads();

    // lane-constant address pieces
    const int arow = 16 * sw + ((lid >> 3) & 1) * 8 + (lid & 7);
    const int bln  = ((lid >> 3) & 1) * 8 + (lid & 7);
    const int khalf = (lid >> 4);
    const int l7    = lid & 7;
    const uint32_t bswz = (uint32_t)((bln >> 1) & 3);
    const uint32_t abase = smb + A0_OFF + (uint32_t)(arow * 512);
    const uint32_t bbase_n = (uint32_t)((nq * 64 + bln) * 64);
    const int wks = wid & 1;            // warp-specific ks order (address-only)

    #pragma unroll 1
    for (int l = 0; l < NHID; ++l) {
        float d[8][4];
        #pragma unroll
        for (int j = 0; j < 8; ++j) {
            d[j][0] = 0.f; d[j][1] = 0.f; d[j][2] = 0.f; d[j][3] = 0.f;
        }

        #pragma unroll 1
        for (int c = 0; c < NCHUNK; ++c) {
            const int ci = l * NCHUNK + c;
            const int v  = ci / 3;
            const int st = ci - v * 3;
            mbar_wait(smb + CTRL_OFF + st * 8, (uint32_t)(v & 1));

            const uint32_t Bst = smb + B_OFF + st * 32768;
            #pragma unroll
            for (int ksx = 0; ksx < 2; ++ksx) {
                const int ks = ksx ^ wks;        // address-only; d[] subscripts stay static
                int aku = c * 4 + ks * 2 + khalf;
                uint32_t aaddr = abase + (uint32_t)((aku ^ l7) << 4);
                uint32_t a0, a1, a2, a3, e0, e1, e2, e3;
                ldmx4(a0, a1, a2, a3, aaddr);
                ldmx4(e0, e1, e2, e3, aaddr + (A1_OFF - A0_OFF));

                uint32_t u = (uint32_t)(ks * 2 + khalf);
                uint32_t blane = Bst + bbase_n + ((u ^ bswz) << 4);
                #pragma unroll
                for (int j2 = 0; j2 < 4; ++j2) {   // STATIC — keeps d[] in registers
                    uint32_t b0, b1, b2, b3;
                    ldmx4(b0, b1, b2, b3, blane + (uint32_t)(j2 * 1024));
                    mma_bf16(d[2 * j2],     a0, a1, a2, a3, b0, b2);
                    mma_bf16(d[2 * j2 + 1], a0, a1, a2, a3, b1, b3);
                    mma_bf16(d[2 * j2],     e0, e1, e2, e3, b0, b2);   // A1*B0
                    mma_bf16(d[2 * j2 + 1], e0, e1, e2, e3, b1, b3);
                    uint32_t c0, c1, c2, c3;
                    ldmx4(c0, c1, c2, c3, blane + 16384u + (uint32_t)(j2 * 1024));
                    mma_bf16(d[2 * j2],     a0, a1, a2, a3, c0, c2);   // A0*B1
                    mma_bf16(d[2 * j2 + 1], a0, a1, a2, a3, c1, c3);
                }
            }
            // last-arriver issues the refill for chunk ci+3 into this stage
            if (lid == 0) {
                int old = atomicAdd(&cnt_sm[st], 1);
                if (old == 31) {
                    cnt_sm[st] = 0;
                    int cr = ci + 3;
                    if (cr < TOTCH) {
                        int l2 = cr >> 3, c2 = cr & 7;
                        uint32_t dst = smb + B_OFF + st * 32768;
                        mbar_expect(smb + CTRL_OFF + st * 8, 32768);
                        bulk_g2s(dst, &g_B[l2][c2][0][0][0], 32768, smb + CTRL_OFF + st * 8);
                    }
                }
            }
        }

        // -------- epilogue --------
        if (l == NHID - 1) __syncthreads();
        else               bar_stripe(1 + sw);

        const float cl = 10.0f * __ldg(&act[l + 1]);
        const int ch   = lid >> 2;
        const int lq   = lid & 3;
        const int srcv = lq, srcx = 4 | lq, srcy = 8 | lq;
        const int rA = 16 * sw + ch, rB = 16 * sw + 8 + ch;
        const int sA = 2 * sw, sB = 2 * sw + 1;
        float* hsb = (float*)sm;

        #pragma unroll
        for (int j = 0; j < 8; ++j) {
            int n0 = nq * 64 + 8 * j + 2 * lq;
            float bv0 = 0.f, bv1 = 0.f;
            if (n0 < HU) {
                float2 bb = *(const float2*)&b_h[l * HU + n0];
                bv0 = bb.x; bv1 = bb.y;
            }

            float zv0 = __shfl_sync(0xffffffffu, d[j][0], srcv);
            float zv1 = __shfl_sync(0xffffffffu, d[j][1], srcv);
            float wv0 = __shfl_sync(0xffffffffu, d[j][2], srcv);
            float wv1 = __shfl_sync(0xffffffffu, d[j][3], srcv);

            // one tanh per lane, deduped across the 8 channel-lanes of this quad
            int e = ch & 3;
            float arg = (e == 0) ? (zv0 + bv0) : (e == 1) ? (zv1 + bv1)
                      : (e == 2) ? (wv0 + bv0) : (wv1 + bv1);
            float tres = tanhf(cl * arg);
            float fA0 = __shfl_sync(0xffffffffu, tres, lq);
            float fA1 = __shfl_sync(0xffffffffu, tres, 4  | lq);
            float fB0 = __shfl_sync(0xffffffffu, tres, 8  | lq);
            float fB1 = __shfl_sync(0xffffffffu, tres, 12 | lq);

            float zx0 = __shfl_sync(0xffffffffu, d[j][0], srcx);
            float zx1 = __shfl_sync(0xffffffffu, d[j][1], srcx);
            float zy0 = __shfl_sync(0xffffffffu, d[j][0], srcy);
            float zy1 = __shfl_sync(0xffffffffu, d[j][1], srcy);
            float hA0 = elemh2(ch, cl, d[j][0], fA0, zx0, zy0);
            float hA1 = elemh2(ch, cl, d[j][1], fA1, zx1, zy1);

            float wx0 = __shfl_sync(0xffffffffu, d[j][2], srcx);
            float wx1 = __shfl_sync(0xffffffffu, d[j][3], srcx);
            float wy0 = __shfl_sync(0xffffffffu, d[j][2], srcy);
            float wy1 = __shfl_sync(0xffffffffu, d[j][3], srcy);
            float hB0 = elemh2(ch, cl, d[j][2], fB0, wx0, wy0);
            float hB1 = elemh2(ch, cl, d[j][3], fB1, wx1, wy1);

            if (n0 >= HU)     { hA0 = 0.f; hB0 = 0.f; }
            if (n0 + 1 >= HU) { hA1 = 0.f; hB1 = 0.f; }

            int unit = nq * 8 + j;
            if (l < NHID - 1) {
                uint32_t offA = (uint32_t)(rA * 512 + ((unit ^ (rA & 7)) << 4) + (n0 & 7) * 2);
                uint32_t offB = (uint32_t)(rB * 512 + ((unit ^ (rB & 7)) << 4) + (n0 & 7) * 2);
                float lA0 = hA0 - __bfloat162float(__float2bfloat16(hA0));
                float lA1 = hA1 - __bfloat162float(__float2bfloat16(hA1));
                float lB0 = hB0 - __bfloat162float(__float2bfloat16(hB0));
                float lB1 = hB1 - __bfloat162float(__float2bfloat16(hB1));
                *(uint32_t*)(sm + A0_OFF + offA) = pack_bf16x2(hA0, hA1);
                *(uint32_t*)(sm + A1_OFF + offA) = pack_bf16x2(lA0, lA1);
                *(uint32_t*)(sm + A0_OFF + offB) = pack_bf16x2(hB0, hB1);
                *(uint32_t*)(sm + A1_OFF + offB) = pack_bf16x2(lB0, lB1);
            } else {
                if (n0 < HU) {
                    hsb[(sA * 256 + n0) * 8 + ch] = hA0;
                    hsb[(sB * 256 + n0) * 8 + ch] = hB0;
                }
                if (n0 + 1 < HU) {
                    hsb[(sA * 256 + n0 + 1) * 8 + ch] = hA1;
                    hsb[(sB * 256 + n0 + 1) * 8 + ch] = hB1;
                }
            }
        }
        if (l < NHID - 1) bar_stripe(1 + sw);
    }
    __syncthreads();   // hsb complete

    // -------- output layer: 16 samples x 4 outs x 7 channels --------
    {
        float* hsb = (float*)sm;
        float* zsh = (float*)(sm + ZSH_OFF);
        for (int idx = tid; idx < SPB * 28; idx += NTHREADS) {
            int s = idx / 28, k2 = idx % 28, o = k2 / 7, c = k2 % 7;
            float acc = (c == 0) ? __ldg(&b_out[o]) : 0.f;
            for (int n = 0; n < HU; ++n)
                acc += hsb[(s * 256 + n) * 8 + c] * __ldg(&W_out[n * 4 + o]);
            zsh[(s * 4 + o) * 8 + c] = acc;
        }
    }
    __syncthreads();

    // -------- residual assembly --------
    if (tid < SPB) {
        int s = tid, n = n0g + s;
        if (n < N) {
            float* zsh = (float*)(sm + ZSH_OFF);
            #define Z(o, c) zsh[((s * 4) + (o)) * 8 + (c)]
            float u = Z(0,0), ux = Z(0,1), uy = Z(0,2), ut = Z(0,3), uxx = Z(0,4), uyy = Z(0,5);
            float v = Z(1,0), vx = Z(1,1), vy = Z(1,2), vt = Z(1,3), vxx = Z(1,4), vyy = Z(1,5);
            float pe  = expf(Z(2,0));
            float p_x = pe * Z(2,1);
            float p_y = pe * Z(2,2);
            float z3  = Z(3,0);
            float aa  = 1.0f / (1.0f + expf(-z3));
            float da  = aa * (1.0f - aa);
            float zax = Z(3,1), zay = Z(3,2), zat = Z(3,3);
            float ax = da * zax, ay = da * zay, at2 = da * zat;
            float om = da * (1.0f - 2.0f * aa);
            float axx = om * zax * zax + da * Z(3,4);
            float ayy = om * zay * zay + da * Z(3,5);
            float axy = om * zax * zay + da * Z(3,6);
            #undef Z
            const float MU1 = 1.0f, MU2 = 10.0f;
            const float RHO1 = 100.0f, RHO2 = 1000.0f, RHO_REF = 1000.0f;
            const float ONE_WE = 24.5f / 500.0f;
            const float ONE_FR = 0.49f;
            const float RE_DEN = 500.0f;
            const float EPSC = 2.2204460492503131e-16f;

            float mu  = MU2 + (MU1 - MU2) * aa;
            float mux = (MU1 - MU2) * ax;
            float muy = (MU1 - MU2) * ay;
            float rho = RHO2 + (RHO1 - RHO2) * aa;
            float g   = sqrtf(ax * ax + ay * ay + EPSC);
            float g3  = g * g * g;
            float curv = -((axx + ayy) / g -
                           (ax * ax * axx + ay * ay * ayy + 2.0f * ax * ay * axy) / g3);
            float oRe  = mu  / RE_DEN;
            float oRex = mux / RE_DEN;
            float oRey = muy / RE_DEN;
            float rr   = rho / RHO_REF;

            float PDE_m = ux + vy;
            float PDE_a = at2 + u * ax + v * ay;
            float PDE_u = (ut + u * ux + v * uy) * rr + p_x - ONE_WE * curv * ax
                        - oRe * (uxx + uyy) - 2.0f * oRex * ux - oRey * (uy + vx);
            float PDE_v = (vt + u * vx + v * vy) * rr + p_y - ONE_WE * curv * ay
                        - oRe * (vxx + vyy) - rr * ONE_FR - 2.0f * oRey * vy - oRex * (uy + vx);

            out[0 * N + n] = PDE_m;
            out[1 * N + n] = PDE_u;
            out[2 * N + n] = PDE_v;
            out[3 * N + n] = PDE_a;
        }
    }
    __syncthreads();
    if (tid == 0) {
        #pragma unroll
        for (int s = 0; s < 3; ++s)
            asm volatile("mbarrier.inval.shared.b64 [%0];" :: "r"(smb + CTRL_OFF + s * 8) : "memory");
    }
}

extern "C" void kernel_launch(void* const* d_in, const int* in_sizes, int n_in,
                              void* d_out, int out_size)
{
    const float* x     = (const float*)d_in[0];
    const float* y     = (const float*)d_in[1];
    const float* t     = (const float*)d_in[2];
    const float* W_in  = (const float*)d_in[3];
    const float* b_in  = (const float*)d_in[4];
    const float* W_h   = (const float*)d_in[5];
    const float* b_h   = (const float*)d_in[6];
    const float* W_out = (const float*)d_in[7];
    const float* b_out = (const float*)d_in[8];
    const float* act   = (const float*)d_in[9];
    float* out = (float*)d_out;
    int N = in_sizes[0];

    cudaFuncSetAttribute(pinn_mma_kernel,
                         cudaFuncAttributeMaxDynamicSharedMemorySize, SMEM_BYTES);

    prep_kernel<<<(NHID * NCHUNK * 256 * 32 + 255) / 256, 256>>>(W_h);

    int blocks = (N + SPB - 1) / SPB;
    pinn_mma_kernel<<<blocks, NTHREADS, SMEM_BYTES>>>(
        x, y, t, W_in, b_in, b_h, W_out, b_out, act, out, N);
}